// round 16
// baseline (speedup 1.0000x reference)
#include <cuda_runtime.h>
#include <cuda_bf16.h>
#include <cuda_fp16.h>
#include <math_constants.h>
#include <cstdint>

// Problem constants
#define NMAX 50000
#define EMAX 300000
#define GNUM 64
#define VOCAB 10000

// ===================== PTX helpers (base-target only: sm_80+ features) ======
__device__ __forceinline__ uint32_t smem_u32(const void* p) {
    uint32_t a;
    asm("{ .reg .u64 t; cvta.to.shared.u64 t, %1; cvt.u32.u64 %0, t; }" : "=r"(a) : "l"(p));
    return a;
}
__device__ __forceinline__ void cp16(uint32_t dst, const void* src, bool valid) {
    asm volatile("cp.async.cg.shared.global [%0], [%1], 16, %2;"
                 :: "r"(dst), "l"(src), "r"(valid ? 16 : 0));
}
#define CP_COMMIT() asm volatile("cp.async.commit_group;" ::: "memory")
#define CP_WAIT(n)  asm volatile("cp.async.wait_group %0;" :: "n"(n) : "memory")

__device__ __forceinline__ void ldsm4(uint32_t r[4], uint32_t addr) {
    asm volatile("ldmatrix.sync.aligned.m8n8.x4.shared.b16 {%0,%1,%2,%3}, [%4];"
                 : "=r"(r[0]), "=r"(r[1]), "=r"(r[2]), "=r"(r[3]) : "r"(addr));
}
__device__ __forceinline__ void mma_bf16(float c[4], const uint32_t a[4],
                                         uint32_t b0, uint32_t b1) {
    asm volatile(
        "mma.sync.aligned.m16n8k16.row.col.f32.bf16.bf16.f32 "
        "{%0,%1,%2,%3}, {%4,%5,%6,%7}, {%8,%9}, {%0,%1,%2,%3};"
        : "+f"(c[0]), "+f"(c[1]), "+f"(c[2]), "+f"(c[3])
        : "r"(a[0]), "r"(a[1]), "r"(a[2]), "r"(a[3]), "r"(b0), "r"(b1));
}

// ===================== scratch (device globals) ==============================
__device__ __nv_bfloat16 g_embhi[VOCAB * 64];   // pre-split embedding table
__device__ __nv_bfloat16 g_emblo[VOCAB * 64];
__device__ __nv_bfloat16 g_hhi[(size_t)NMAX * 256];
__device__ __nv_bfloat16 g_hlo[(size_t)NMAX * 256];
__device__ __nv_bfloat16 g_whi[1024 * 512];
__device__ __nv_bfloat16 g_wlo[1024 * 512];
__device__ float g_bias[1024];
__device__ float  g_q[(size_t)NMAX * 256];      // fp32 query (evict-first streams)
__device__ __half g_kv[(size_t)NMAX * 512];     // fp16 [k|v] per node (L2-resident)
__device__ float  g_skip[(size_t)NMAX * 256];   // fp32 skip term (evict-first)
__device__ float  g_h1[(size_t)NMAX * 256];
__device__ int   g_deg[NMAX];
__device__ int   g_rowptr[NMAX + 1];
__device__ int   g_cursor[NMAX];
__device__ int   g_srcs[EMAX];                  // CSR-sorted src node ids
__device__ float g_eattr_s[(size_t)EMAX * 6];   // CSR-sorted edge attributes
__device__ int   g_bsum[256];
__device__ int   g_boff[256];
__device__ float g_gap[GNUM * 256];
__device__ unsigned g_gmp[GNUM * 256];
__device__ int   g_cnt[GNUM];
__device__ int            g_bar_cnt;        // zero-init
__device__ volatile int   g_bar_gen;        // monotonically increasing

__device__ __forceinline__ void split_bf16(float v, __nv_bfloat16& hi, __nv_bfloat16& lo) {
    hi = __float2bfloat16(v);
    lo = __float2bfloat16(v - __bfloat162float(hi));
}

// ---------------- software grid barrier (all blocks resident) ----------------
__device__ __forceinline__ void gsync()
{
    __syncthreads();
    if (threadIdx.x == 0) {
        int g = g_bar_gen;
        __threadfence();
        if (atomicAdd(&g_bar_cnt, 1) == (int)gridDim.x - 1) {
            g_bar_cnt = 0;
            __threadfence();
            g_bar_gen = g + 1;
        } else {
            while (g_bar_gen == g) __nanosleep(64);
        }
        __threadfence();
    }
    __syncthreads();
}

// ---------------- 0. embedding table split (once) ----------------------------
__global__ void embsplit_kernel(const float* __restrict__ emb)
{
    int i = blockIdx.x * blockDim.x + threadIdx.x;
    if (i >= VOCAB * 64) return;
    __nv_bfloat16 hi, lo; split_bf16(emb[i], hi, lo);
    g_embhi[i] = hi; g_emblo[i] = lo;
}

// ---------------- 1. weight split: rows [wq|wk|wv|ws] -> g_whi/g_wlo ---------
__global__ void splitw_kernel(const float* __restrict__ wq, const float* __restrict__ wk,
                              const float* __restrict__ wv, const float* __restrict__ ws,
                              const float* __restrict__ bq, const float* __restrict__ bk,
                              const float* __restrict__ bv, const float* __restrict__ bs,
                              int K)
{
    long idx = (long)blockIdx.x * blockDim.x + threadIdx.x;
    if (idx < 1024) {
        int r = (int)idx;
        const float* bb = (r < 256) ? bq : (r < 512) ? bk : (r < 768) ? bv : bs;
        g_bias[r] = bb[r & 255];
    }
    if (idx >= (long)1024 * K) return;
    int row = (int)(idx / K), col = (int)(idx % K);
    const float* W = (row < 256) ? wq : (row < 512) ? wk : (row < 768) ? wv : ws;
    float v = W[(row & 255) * K + col];
    __nv_bfloat16 hi, lo; split_bf16(v, hi, lo);
    g_whi[idx] = hi; g_wlo[idx] = lo;
}

// ---------------- 2. fused CSR build + pooling-buffer init (one launch) ------
#define CSRB 148
__global__ void __launch_bounds__(256) csr_kernel(
    const int* __restrict__ esrc, const int* __restrict__ dst,
    const float* __restrict__ eattr, int E, int N)
{
    int tid = threadIdx.x, bid = blockIdx.x;
    int gt = bid * 256 + tid;
    int GT = (int)gridDim.x * 256;
    __shared__ int sm[256];

    for (int i = gt; i < N; i += GT) g_deg[i] = 0;
    for (int i = gt; i < GNUM * 256; i += GT) { g_gap[i] = 0.f; g_gmp[i] = 0u; }
    for (int i = gt; i < GNUM; i += GT) g_cnt[i] = 0;
    gsync();

    for (int e = gt; e < E; e += GT) atomicAdd(&g_deg[dst[e]], 1);
    gsync();

    int n0 = gt * 2;
    int dv0 = (n0 < N) ? g_deg[n0] : 0;
    int dv1 = (n0 + 1 < N) ? g_deg[n0 + 1] : 0;
    int tsum = dv0 + dv1;
    sm[tid] = tsum;
    __syncthreads();
    #pragma unroll
    for (int off = 1; off < 256; off <<= 1) {
        int t = (tid >= off) ? sm[tid - off] : 0;
        __syncthreads();
        sm[tid] += t;
        __syncthreads();
    }
    int incl = sm[tid];
    int excl = incl - tsum;
    if (tid == 255) g_bsum[bid] = incl;
    gsync();

    if (bid == 0) {
        int v = (tid < (int)gridDim.x) ? g_bsum[tid] : 0;
        __syncthreads();
        sm[tid] = v;
        __syncthreads();
        #pragma unroll
        for (int off = 1; off < 256; off <<= 1) {
            int t = (tid >= off) ? sm[tid - off] : 0;
            __syncthreads();
            sm[tid] += t;
            __syncthreads();
        }
        if (tid < (int)gridDim.x) g_boff[tid] = sm[tid] - v;
    }
    gsync();

    int base = g_boff[bid] + excl;
    if (n0 < N)     { g_rowptr[n0 + 1] = base + dv0;       g_cursor[n0]     = base; }
    if (n0 + 1 < N) { g_rowptr[n0 + 2] = base + dv0 + dv1; g_cursor[n0 + 1] = base + dv0; }
    if (gt == 0) g_rowptr[0] = 0;
    gsync();

    for (int e = gt; e < E; e += GT) {
        int pos = atomicAdd(&g_cursor[dst[e]], 1);
        g_srcs[pos] = esrc[e];
        float2 a0 = *(const float2*)(eattr + (size_t)e * 6);
        float2 a1 = *(const float2*)(eattr + (size_t)e * 6 + 2);
        float2 a2 = *(const float2*)(eattr + (size_t)e * 6 + 4);
        float* dp = g_eattr_s + (size_t)pos * 6;
        dp[0] = a0.x; dp[1] = a0.y; dp[2] = a1.x;
        dp[3] = a1.y; dp[4] = a2.x; dp[5] = a2.y;
    }
}

// ---------------- 3. mma.sync GEMM -------------------------------------------
// Single __syncthreads per K-iteration; BOTH layers now use pure cp.async
// A-paths (layer 0 gathers from the pre-split embedding tables).
#define BM 128
#define BN 128
#define BK 32
#define LDT 80
#define TILE_SZ (BM * LDT)
#define STAGE_SZ (4 * TILE_SZ)
#define NSTAGE 2
#define GEMM_SMEM (NSTAGE * STAGE_SZ)   // 81920 B -> 2 CTAs/SM

template<int LAYER>
__global__ void __launch_bounds__(256, 2) gemm_tc(int M, int K,
    const int* __restrict__ xidx)
{
    extern __shared__ char smem[];
    uint32_t sb = smem_u32(smem);

    int tid = threadIdx.x;
    int m0 = blockIdx.y * BM;
    int n0 = blockIdx.x * BN;
    int wid = tid >> 5, lane = tid & 31;
    int wm = wid & 1, wn = wid >> 1;

    float C[4][4][4];
    #pragma unroll
    for (int a = 0; a < 4; a++)
        #pragma unroll
        for (int b = 0; b < 4; b++)
            #pragma unroll
            for (int c = 0; c < 4; c++) C[a][b][c] = 0.f;

    int S = K / BK;

    auto loadA = [&](int s) {
        int k0 = s * BK;
        uint32_t base = sb + (s & 1) * STAGE_SZ;
        if (LAYER == 0) {
            // gather from pre-split embedding tables via cp.async
            int f = k0 >> 6, j0 = k0 & 63;     // constant within a stage (BK=32)
            #pragma unroll
            for (int i = 0; i < 2; i++) {
                int c = i * 256 + tid;          // 0..511
                int row = c >> 2;               // 128 rows
                int co = c & 3;                 // 4 x 16B chunks (8 bf16 each)
                uint32_t doff = row * LDT + co * 16;
                int m = m0 + row;
                bool v = m < M;
                int vb = v ? __ldg(xidx + m * 8 + f) : 0;
                size_t eb = (size_t)vb * 64 + j0 + co * 8;
                cp16(base + doff,           g_embhi + eb, v);
                cp16(base + TILE_SZ + doff, g_emblo + eb, v);
            }
        } else {
            #pragma unroll
            for (int i = 0; i < 2; i++) {
                int c = i * 256 + tid;
                int row = c >> 2;
                int co = c & 3;
                uint32_t doff = row * LDT + co * 16;
                long ka = (long)k0 + co * 8;
                bool v = (m0 + row) < M;
                cp16(base + doff,           g_hhi + (size_t)(m0 + row) * K + ka, v);
                cp16(base + TILE_SZ + doff, g_hlo + (size_t)(m0 + row) * K + ka, v);
            }
        }
    };
    auto loadB = [&](int s) {
        int k0 = s * BK;
        uint32_t base = sb + (s & 1) * STAGE_SZ;
        #pragma unroll
        for (int i = 0; i < 2; i++) {
            int c = i * 256 + tid;
            int row = c >> 2;
            int co = c & 3;
            uint32_t doff = row * LDT + co * 16;
            long ka = (long)k0 + co * 8;
            size_t gb = (size_t)(n0 + row) * K + ka;
            cp16(base + 2 * TILE_SZ + doff, g_whi + gb, true);
            cp16(base + 3 * TILE_SZ + doff, g_wlo + gb, true);
        }
    };

    loadA(0); loadB(0); CP_COMMIT();

    for (int s = 0; s < S; s++) {
        CP_WAIT(0);            // stage-s data complete
        __syncthreads();       // publish + buffer-reuse safety
        if (s + 1 < S) { loadA(s + 1); loadB(s + 1); CP_COMMIT(); }  // overlaps compute
        uint32_t base = sb + (s & 1) * STAGE_SZ;

        #pragma unroll
        for (int ks = 0; ks < 2; ks++) {
            uint32_t Ah[4][4], Al[4][4];
            int arow = wm * 64 + (lane & 15);
            uint32_t acol = ks * 32 + (lane >> 4) * 16;
            #pragma unroll
            for (int mt = 0; mt < 4; mt++) {
                uint32_t ad = base + (arow + mt * 16) * LDT + acol;
                ldsm4(Ah[mt], ad);
                ldsm4(Al[mt], ad + TILE_SZ);
            }
            #pragma unroll
            for (int p = 0; p < 2; p++) {
                int mat = lane >> 3, r = lane & 7;
                int brow = wn * 32 + p * 16 + (mat >> 1) * 8 + r;
                uint32_t bcol = ks * 32 + (mat & 1) * 16;
                uint32_t bd = base + 2 * TILE_SZ + brow * LDT + bcol;
                uint32_t Bh[4], Bl[4];
                ldsm4(Bh, bd);
                ldsm4(Bl, bd + TILE_SZ);
                #pragma unroll
                for (int mt = 0; mt < 4; mt++) {
                    #pragma unroll
                    for (int j = 0; j < 2; j++) {
                        float* cc = C[mt][p * 2 + j];
                        mma_bf16(cc, Ah[mt], Bh[j * 2], Bh[j * 2 + 1]);
                        mma_bf16(cc, Ah[mt], Bl[j * 2], Bl[j * 2 + 1]);
                        mma_bf16(cc, Al[mt], Bh[j * 2], Bh[j * 2 + 1]);
                    }
                }
            }
        }
    }

    // ---- epilogue: bias + routed store (q/skip evict-first, kv default)
    #pragma unroll
    for (int mt = 0; mt < 4; mt++) {
        int m = m0 + wm * 64 + mt * 16 + (lane >> 2);
        #pragma unroll
        for (int nt = 0; nt < 4; nt++) {
            int col = n0 + wn * 32 + nt * 8 + (lane & 3) * 2;
            float b0 = g_bias[col], b1 = g_bias[col + 1];
            int seg = col >> 8;
            #pragma unroll
            for (int h = 0; h < 2; h++) {
                int mm = m + h * 8;
                if (mm >= M) continue;
                float v0 = C[mt][nt][h * 2] + b0;
                float v1 = C[mt][nt][h * 2 + 1] + b1;
                if (seg == 0) {
                    __stcs((float2*)(g_q + (size_t)mm * 256 + col), make_float2(v0, v1));
                } else if (seg == 3) {
                    __stcs((float2*)(g_skip + (size_t)mm * 256 + (col - 768)), make_float2(v0, v1));
                } else {
                    *(__half2*)(g_kv + (size_t)mm * 512 + (col - 256)) = __floats2half2_rn(v0, v1);
                }
            }
        }
    }
}

// ---------------- 4. fused edge attention: 1 warp per dst node --------------
// FROZEN champion: CSR-sorted operands, streaming hints, natural regs.
__global__ void __launch_bounds__(256) attn_kernel(
    int layer, const float* __restrict__ we, const float* __restrict__ be, int N)
{
    int warp = (int)((blockIdx.x * 256 + threadIdx.x) >> 5);
    int lane = threadIdx.x & 31;
    if (warp >= N) return;

    int d0 = lane * 8;
    float wE[8][6], bE[8];
    #pragma unroll
    for (int i = 0; i < 8; i++) {
        bE[i] = be[d0 + i];
        #pragma unroll
        for (int j = 0; j < 6; j++) wE[i][j] = we[(d0 + i) * 6 + j];
    }

    float q[8];
    {
        const float* qp = g_q + (size_t)warp * 256 + d0;
        float4 t0 = __ldcs((const float4*)qp);
        float4 t1 = __ldcs((const float4*)(qp + 4));
        q[0] = t0.x; q[1] = t0.y; q[2] = t0.z; q[3] = t0.w;
        q[4] = t1.x; q[5] = t1.y; q[6] = t1.z; q[7] = t1.w;
    }

    float qb = 0.f;
    #pragma unroll
    for (int i = 0; i < 8; i++) qb += q[i] * bE[i];
    float qw[6];
    #pragma unroll
    for (int j = 0; j < 6; j++) {
        float t = 0.f;
        #pragma unroll
        for (int i = 0; i < 8; i++) t += q[i] * wE[i][j];
        qw[j] = t;
    }
    #pragma unroll
    for (int off = 16; off; off >>= 1) {
        qb += __shfl_xor_sync(0xffffffffu, qb, off);
        #pragma unroll
        for (int j = 0; j < 6; j++) qw[j] += __shfl_xor_sync(0xffffffffu, qw[j], off);
    }

    float m = -CUDART_INF_F, s = 0.f;
    float acc[8] = {0, 0, 0, 0, 0, 0, 0, 0};
    float te[6]  = {0, 0, 0, 0, 0, 0};
    int p = g_rowptr[warp], end = g_rowptr[warp + 1];

    int src = 0;
    if (p < end) src = g_srcs[p];

    for (; p < end; p++) {
        const __half* kb = g_kv + (size_t)src * 512 + d0;
        uint4 ku = *(const uint4*)kb;
        uint4 vu = *(const uint4*)(kb + 256);
        float e[6];
        #pragma unroll
        for (int j = 0; j < 6; j++) e[j] = __ldg(g_eattr_s + (size_t)p * 6 + j);

        if (p + 1 < end) src = g_srcs[p + 1];

        float qk = 0.f;
        {
            const __half2* kp = (const __half2*)&ku;
            #pragma unroll
            for (int i = 0; i < 4; i++) {
                float2 kf = __half22float2(kp[i]);
                qk += q[i * 2] * kf.x + q[i * 2 + 1] * kf.y;
            }
        }
        #pragma unroll
        for (int off = 16; off; off >>= 1) qk += __shfl_xor_sync(0xffffffffu, qk, off);

        float qe = qb;
        #pragma unroll
        for (int j = 0; j < 6; j++) qe += qw[j] * e[j];
        float logit = (qk + qe) * 0.0625f;

        float nm = fmaxf(m, logit);
        float sc = __expf(m - nm);
        float pw = __expf(logit - nm);
        s = s * sc + pw;
        #pragma unroll
        for (int j = 0; j < 6; j++) te[j] = te[j] * sc + pw * e[j];
        {
            const __half2* vp = (const __half2*)&vu;
            #pragma unroll
            for (int i = 0; i < 4; i++) {
                float2 vf = __half22float2(vp[i]);
                acc[i * 2]     = acc[i * 2]     * sc + pw * vf.x;
                acc[i * 2 + 1] = acc[i * 2 + 1] * sc + pw * vf.y;
            }
        }
        m = nm;
    }

    float inv = (s > 0.f) ? (1.f / s) : 0.f;
    float one = (s > 0.f) ? 1.f : 0.f;
    float tn[6];
    #pragma unroll
    for (int j = 0; j < 6; j++) tn[j] = te[j] * inv;

    const float* sk = g_skip + (size_t)warp * 256 + d0;
    float4 s0 = __ldcs((const float4*)sk);
    float4 s1 = __ldcs((const float4*)(sk + 4));
    float skp[8] = {s0.x, s0.y, s0.z, s0.w, s1.x, s1.y, s1.z, s1.w};

    float o[8];
    #pragma unroll
    for (int i = 0; i < 8; i++) {
        float t = acc[i] * inv + bE[i] * one + skp[i];
        #pragma unroll
        for (int j = 0; j < 6; j++) t += wE[i][j] * tn[j];
        o[i] = fmaxf(t, 0.f);
    }

    if (layer == 0) {
        uint4 uh, ul;
        __nv_bfloat16* ph = (__nv_bfloat16*)&uh;
        __nv_bfloat16* pl = (__nv_bfloat16*)&ul;
        #pragma unroll
        for (int i = 0; i < 8; i++) {
            __nv_bfloat16 hi, lo; split_bf16(o[i], hi, lo);
            ph[i] = hi; pl[i] = lo;
        }
        __stcs((uint4*)(g_hhi + (size_t)warp * 256 + d0), uh);
        __stcs((uint4*)(g_hlo + (size_t)warp * 256 + d0), ul);
    } else {
        float* hp = g_h1 + (size_t)warp * 256 + d0;
        __stcs((float4*)hp,       *(const float4*)&o[0]);
        __stcs((float4*)(hp + 4), *(const float4*)&o[4]);
    }
}

// ---------------- 5. pooling (sorted batch, run-accumulated atomics) --------
#define POOL_CHUNK 128
__global__ void __launch_bounds__(256) pool_kernel(const int* __restrict__ batch, int N)
{
    int d  = threadIdx.x;
    int n0 = blockIdx.x * POOL_CHUNK;
    if (n0 >= N) return;
    int n1 = min(n0 + POOL_CHUNK, N);

    int cur = batch[n0];
    float sum = 0.f, mx = 0.f;
    int run = 0;
    for (int n = n0; n < n1; n++) {
        int g = batch[n];
        if (g != cur) {
            atomicAdd(&g_gap[cur * 256 + d], sum);
            atomicMax(&g_gmp[cur * 256 + d], __float_as_uint(mx));
            if (d == 0) atomicAdd(&g_cnt[cur], run);
            sum = 0.f; mx = 0.f; run = 0; cur = g;
        }
        float v = __ldcs(g_h1 + (size_t)n * 256 + d);
        sum += v; mx = fmaxf(mx, v); run++;
    }
    atomicAdd(&g_gap[cur * 256 + d], sum);
    atomicMax(&g_gmp[cur * 256 + d], __float_as_uint(mx));
    if (d == 0) atomicAdd(&g_cnt[cur], run);
}

// ---------------- 6. head MLP ------------------------------------------------
__global__ void __launch_bounds__(256) mlp_kernel(
    const float* __restrict__ w1, const float* __restrict__ b1,
    const float* __restrict__ w2, const float* __restrict__ b2,
    const float* __restrict__ w3, const float* __restrict__ b3,
    float* __restrict__ out)
{
    int g = blockIdx.x;
    int t = threadIdx.x;
    __shared__ float r[512];
    __shared__ float o1[256];
    __shared__ float o2[128];
    __shared__ float red[256];

    float c = fmaxf((float)g_cnt[g], 1.f);
    r[t]       = g_gap[g * 256 + t] / c;
    r[256 + t] = __uint_as_float(g_gmp[g * 256 + t]);
    __syncthreads();
    {
        float a = b1[t];
        const float* wr = w1 + (size_t)t * 512;
        #pragma unroll 8
        for (int i = 0; i < 512; i++) a += wr[i] * r[i];
        o1[t] = fmaxf(a, 0.f);
    }
    __syncthreads();
    if (t < 128) {
        float a = b2[t];
        const float* wr = w2 + (size_t)t * 256;
        #pragma unroll 8
        for (int i = 0; i < 256; i++) a += wr[i] * o1[i];
        o2[t] = fmaxf(a, 0.f);
    }
    __syncthreads();
    red[t] = (t < 128) ? w3[t] * o2[t] : 0.f;
    __syncthreads();
    for (int off = 128; off > 0; off >>= 1) {
        if (t < off) red[t] += red[t + off];
        __syncthreads();
    }
    if (t == 0) out[g] = 1.f / (1.f + __expf(-(red[0] + b3[0])));
}

// ---------------- launch ------------------------------------------------------
extern "C" void kernel_launch(void* const* d_in, const int* in_sizes, int n_in,
                              void* d_out, int out_size)
{
    const int*   x_idx = (const int*)d_in[0];
    const int*   eidx  = (const int*)d_in[1];
    const float* eattr = (const float*)d_in[2];
    const int*   batch = (const int*)d_in[3];
    const float* emb   = (const float*)d_in[4];
    const float* c1[10]; for (int i = 0; i < 10; i++) c1[i] = (const float*)d_in[5 + i];
    const float* c2[10]; for (int i = 0; i < 10; i++) c2[i] = (const float*)d_in[15 + i];
    const float* w1 = (const float*)d_in[25]; const float* b1 = (const float*)d_in[26];
    const float* w2 = (const float*)d_in[27]; const float* b2 = (const float*)d_in[28];
    const float* w3 = (const float*)d_in[29]; const float* b3 = (const float*)d_in[30];

    int N = in_sizes[0] / 8;    // 50000
    int E = in_sizes[1] / 2;    // 300000
    const int* esrc = eidx;
    const int* edst = eidx + E;
    float* out = (float*)d_out;

    cudaFuncSetAttribute(gemm_tc<0>, cudaFuncAttributeMaxDynamicSharedMemorySize, GEMM_SMEM);
    cudaFuncSetAttribute(gemm_tc<1>, cudaFuncAttributeMaxDynamicSharedMemorySize, GEMM_SMEM);

    dim3 ggrid(8, (N + 127) / 128);

    // gemm1 at capture index 3 this round (attn is converged; verify gemm).
    embsplit_kernel<<<(VOCAB * 64 + 255) / 256, 256>>>(emb);                           // 0
    splitw_kernel<<<(1024 * 512 + 255) / 256, 256>>>(
        c1[0], c1[2], c1[4], c1[8], c1[1], c1[3], c1[5], c1[9], 512);                  // 1
    csr_kernel<<<CSRB, 256>>>(esrc, edst, eattr, E, N);                                // 2
    gemm_tc<0><<<ggrid, 256, GEMM_SMEM>>>(N, 512, x_idx);                              // 3 <- profiled
    attn_kernel<<<(N + 7) / 8, 256>>>(0, c1[6], c1[7], N);                             // 4
    splitw_kernel<<<(1024 * 256 + 255) / 256, 256>>>(
        c2[0], c2[2], c2[4], c2[8], c2[1], c2[3], c2[5], c2[9], 256);                  // 5
    gemm_tc<1><<<ggrid, 256, GEMM_SMEM>>>(N, 256, nullptr);                            // 6
    attn_kernel<<<(N + 7) / 8, 256>>>(1, c2[6], c2[7], N);                             // 7
    pool_kernel<<<(N + POOL_CHUNK - 1) / POOL_CHUNK, 256>>>(batch, N);                 // 8
    mlp_kernel<<<GNUM, 256>>>(w1, b1, w2, b2, w3, b3, out);                            // 9
}

// round 17
// speedup vs baseline: 1.1563x; 1.1563x over previous
#include <cuda_runtime.h>
#include <cuda_bf16.h>
#include <cuda_fp16.h>
#include <math_constants.h>
#include <cstdint>

// Problem constants
#define NMAX 50000
#define EMAX 300000
#define GNUM 64
#define VOCAB 10000

// ===================== PTX helpers (base-target only: sm_80+ features) ======
__device__ __forceinline__ uint32_t smem_u32(const void* p) {
    uint32_t a;
    asm("{ .reg .u64 t; cvta.to.shared.u64 t, %1; cvt.u32.u64 %0, t; }" : "=r"(a) : "l"(p));
    return a;
}
__device__ __forceinline__ void cp16(uint32_t dst, const void* src, bool valid) {
    asm volatile("cp.async.cg.shared.global [%0], [%1], 16, %2;"
                 :: "r"(dst), "l"(src), "r"(valid ? 16 : 0));
}
#define CP_COMMIT() asm volatile("cp.async.commit_group;" ::: "memory")
#define CP_WAIT(n)  asm volatile("cp.async.wait_group %0;" :: "n"(n) : "memory")

__device__ __forceinline__ void ldsm4(uint32_t r[4], uint32_t addr) {
    asm volatile("ldmatrix.sync.aligned.m8n8.x4.shared.b16 {%0,%1,%2,%3}, [%4];"
                 : "=r"(r[0]), "=r"(r[1]), "=r"(r[2]), "=r"(r[3]) : "r"(addr));
}
__device__ __forceinline__ void mma_bf16(float c[4], const uint32_t a[4],
                                         uint32_t b0, uint32_t b1) {
    asm volatile(
        "mma.sync.aligned.m16n8k16.row.col.f32.bf16.bf16.f32 "
        "{%0,%1,%2,%3}, {%4,%5,%6,%7}, {%8,%9}, {%0,%1,%2,%3};"
        : "+f"(c[0]), "+f"(c[1]), "+f"(c[2]), "+f"(c[3])
        : "r"(a[0]), "r"(a[1]), "r"(a[2]), "r"(a[3]), "r"(b0), "r"(b1));
}

// ===================== scratch (device globals) ==============================
__device__ __nv_bfloat16 g_embhi[VOCAB * 64];   // bf16 embedding table
__device__ __nv_bfloat16 g_hhi[(size_t)NMAX * 256];   // layer-1 output (bf16)
__device__ __nv_bfloat16 g_whi[1024 * 512];
__device__ __nv_bfloat16 g_wlo[1024 * 512];
__device__ float g_bias[1024];
__device__ float  g_q[(size_t)NMAX * 256];      // fp32 query (evict-first streams)
__device__ __half g_kv[(size_t)NMAX * 512];     // fp16 [k|v] per node (L2-resident)
__device__ float  g_skip[(size_t)NMAX * 256];   // fp32 skip term (evict-first)
__device__ float  g_h1[(size_t)NMAX * 256];
__device__ int   g_deg[NMAX];
__device__ int   g_rowptr[NMAX + 1];
__device__ int   g_cursor[NMAX];
__device__ int   g_srcs[EMAX];                  // CSR-sorted src node ids
__device__ float g_eattr_s[(size_t)EMAX * 6];   // CSR-sorted edge attributes
__device__ int   g_bsum[256];
__device__ int   g_boff[256];
__device__ float g_gap[GNUM * 256];
__device__ unsigned g_gmp[GNUM * 256];
__device__ int   g_cnt[GNUM];
__device__ int            g_bar_cnt;        // zero-init
__device__ volatile int   g_bar_gen;        // monotonically increasing

__device__ __forceinline__ void split_bf16(float v, __nv_bfloat16& hi, __nv_bfloat16& lo) {
    hi = __float2bfloat16(v);
    lo = __float2bfloat16(v - __bfloat162float(hi));
}

// ---------------- software grid barrier (all blocks resident) ----------------
__device__ __forceinline__ void gsync()
{
    __syncthreads();
    if (threadIdx.x == 0) {
        int g = g_bar_gen;
        __threadfence();
        if (atomicAdd(&g_bar_cnt, 1) == (int)gridDim.x - 1) {
            g_bar_cnt = 0;
            __threadfence();
            g_bar_gen = g + 1;
        } else {
            while (g_bar_gen == g) __nanosleep(64);
        }
        __threadfence();
    }
    __syncthreads();
}

// ---------------- 0. embedding table bf16 conversion (once) ------------------
__global__ void embcvt_kernel(const float* __restrict__ emb)
{
    int i = blockIdx.x * blockDim.x + threadIdx.x;
    if (i >= VOCAB * 64) return;
    g_embhi[i] = __float2bfloat16(emb[i]);
}

// ---------------- 1. weight split: rows [wq|wk|wv|ws] -> g_whi/g_wlo ---------
__global__ void splitw_kernel(const float* __restrict__ wq, const float* __restrict__ wk,
                              const float* __restrict__ wv, const float* __restrict__ ws,
                              const float* __restrict__ bq, const float* __restrict__ bk,
                              const float* __restrict__ bv, const float* __restrict__ bs,
                              int K)
{
    long idx = (long)blockIdx.x * blockDim.x + threadIdx.x;
    if (idx < 1024) {
        int r = (int)idx;
        const float* bb = (r < 256) ? bq : (r < 512) ? bk : (r < 768) ? bv : bs;
        g_bias[r] = bb[r & 255];
    }
    if (idx >= (long)1024 * K) return;
    int row = (int)(idx / K), col = (int)(idx % K);
    const float* W = (row < 256) ? wq : (row < 512) ? wk : (row < 768) ? wv : ws;
    float v = W[(row & 255) * K + col];
    __nv_bfloat16 hi, lo; split_bf16(v, hi, lo);
    g_whi[idx] = hi; g_wlo[idx] = lo;
}

// ---------------- 2. fused CSR build + pooling-buffer init (one launch) ------
#define CSRB 148
__global__ void __launch_bounds__(256) csr_kernel(
    const int* __restrict__ esrc, const int* __restrict__ dst,
    const float* __restrict__ eattr, int E, int N)
{
    int tid = threadIdx.x, bid = blockIdx.x;
    int gt = bid * 256 + tid;
    int GT = (int)gridDim.x * 256;
    __shared__ int sm[256];

    for (int i = gt; i < N; i += GT) g_deg[i] = 0;
    for (int i = gt; i < GNUM * 256; i += GT) { g_gap[i] = 0.f; g_gmp[i] = 0u; }
    for (int i = gt; i < GNUM; i += GT) g_cnt[i] = 0;
    gsync();

    for (int e = gt; e < E; e += GT) atomicAdd(&g_deg[dst[e]], 1);
    gsync();

    int n0 = gt * 2;
    int dv0 = (n0 < N) ? g_deg[n0] : 0;
    int dv1 = (n0 + 1 < N) ? g_deg[n0 + 1] : 0;
    int tsum = dv0 + dv1;
    sm[tid] = tsum;
    __syncthreads();
    #pragma unroll
    for (int off = 1; off < 256; off <<= 1) {
        int t = (tid >= off) ? sm[tid - off] : 0;
        __syncthreads();
        sm[tid] += t;
        __syncthreads();
    }
    int incl = sm[tid];
    int excl = incl - tsum;
    if (tid == 255) g_bsum[bid] = incl;
    gsync();

    if (bid == 0) {
        int v = (tid < (int)gridDim.x) ? g_bsum[tid] : 0;
        __syncthreads();
        sm[tid] = v;
        __syncthreads();
        #pragma unroll
        for (int off = 1; off < 256; off <<= 1) {
            int t = (tid >= off) ? sm[tid - off] : 0;
            __syncthreads();
            sm[tid] += t;
            __syncthreads();
        }
        if (tid < (int)gridDim.x) g_boff[tid] = sm[tid] - v;
    }
    gsync();

    int base = g_boff[bid] + excl;
    if (n0 < N)     { g_rowptr[n0 + 1] = base + dv0;       g_cursor[n0]     = base; }
    if (n0 + 1 < N) { g_rowptr[n0 + 2] = base + dv0 + dv1; g_cursor[n0 + 1] = base + dv0; }
    if (gt == 0) g_rowptr[0] = 0;
    gsync();

    for (int e = gt; e < E; e += GT) {
        int pos = atomicAdd(&g_cursor[dst[e]], 1);
        g_srcs[pos] = esrc[e];
        float2 a0 = *(const float2*)(eattr + (size_t)e * 6);
        float2 a1 = *(const float2*)(eattr + (size_t)e * 6 + 2);
        float2 a2 = *(const float2*)(eattr + (size_t)e * 6 + 4);
        float* dp = g_eattr_s + (size_t)pos * 6;
        dp[0] = a0.x; dp[1] = a0.y; dp[2] = a1.x;
        dp[3] = a1.y; dp[4] = a2.x; dp[5] = a2.y;
    }
}

// ---------------- 3. mma.sync GEMM -------------------------------------------
// 2-term split: A in bf16, W = Whi + Wlo. C = A@(Whi+Wlo)^T + bias.
// Per stage: [A | Bhi | Blo] tiles; 64 mma/stage (was 96); single sync/iter.
#define BM 128
#define BN 128
#define BK 32
#define LDT 80
#define TILE_SZ (BM * LDT)
#define STAGE_SZ (3 * TILE_SZ)          // 30720 B
#define GEMM_SMEM (2 * STAGE_SZ)        // 61440 B -> 2 CTAs/SM

template<int LAYER>
__global__ void __launch_bounds__(256, 2) gemm_tc(int M, int K,
    const int* __restrict__ xidx)
{
    extern __shared__ char smem[];
    uint32_t sb = smem_u32(smem);

    int tid = threadIdx.x;
    int m0 = blockIdx.y * BM;
    int n0 = blockIdx.x * BN;
    int wid = tid >> 5, lane = tid & 31;
    int wm = wid & 1, wn = wid >> 1;

    float C[4][4][4];
    #pragma unroll
    for (int a = 0; a < 4; a++)
        #pragma unroll
        for (int b = 0; b < 4; b++)
            #pragma unroll
            for (int c = 0; c < 4; c++) C[a][b][c] = 0.f;

    int S = K / BK;

    auto loadA = [&](int s) {
        int k0 = s * BK;
        uint32_t base = sb + (s & 1) * STAGE_SZ;
        if (LAYER == 0) {
            int f = k0 >> 6, j0 = k0 & 63;
            #pragma unroll
            for (int i = 0; i < 2; i++) {
                int c = i * 256 + tid;          // 0..511
                int row = c >> 2;
                int co = c & 3;
                uint32_t doff = row * LDT + co * 16;
                int m = m0 + row;
                bool v = m < M;
                int vb = v ? __ldg(xidx + m * 8 + f) : 0;
                cp16(base + doff, g_embhi + (size_t)vb * 64 + j0 + co * 8, v);
            }
        } else {
            #pragma unroll
            for (int i = 0; i < 2; i++) {
                int c = i * 256 + tid;
                int row = c >> 2;
                int co = c & 3;
                uint32_t doff = row * LDT + co * 16;
                long ka = (long)k0 + co * 8;
                bool v = (m0 + row) < M;
                cp16(base + doff, g_hhi + (size_t)(m0 + row) * K + ka, v);
            }
        }
    };
    auto loadB = [&](int s) {
        int k0 = s * BK;
        uint32_t base = sb + (s & 1) * STAGE_SZ;
        #pragma unroll
        for (int i = 0; i < 2; i++) {
            int c = i * 256 + tid;
            int row = c >> 2;
            int co = c & 3;
            uint32_t doff = row * LDT + co * 16;
            long ka = (long)k0 + co * 8;
            size_t gb = (size_t)(n0 + row) * K + ka;
            cp16(base + TILE_SZ + doff,     g_whi + gb, true);
            cp16(base + 2 * TILE_SZ + doff, g_wlo + gb, true);
        }
    };

    loadA(0); loadB(0); CP_COMMIT();

    for (int s = 0; s < S; s++) {
        CP_WAIT(0);
        __syncthreads();
        if (s + 1 < S) { loadA(s + 1); loadB(s + 1); CP_COMMIT(); }
        uint32_t base = sb + (s & 1) * STAGE_SZ;

        #pragma unroll
        for (int ks = 0; ks < 2; ks++) {
            uint32_t Ah[4][4];
            int arow = wm * 64 + (lane & 15);
            uint32_t acol = ks * 32 + (lane >> 4) * 16;
            #pragma unroll
            for (int mt = 0; mt < 4; mt++) {
                uint32_t ad = base + (arow + mt * 16) * LDT + acol;
                ldsm4(Ah[mt], ad);
            }
            #pragma unroll
            for (int p = 0; p < 2; p++) {
                int mat = lane >> 3, r = lane & 7;
                int brow = wn * 32 + p * 16 + (mat >> 1) * 8 + r;
                uint32_t bcol = ks * 32 + (mat & 1) * 16;
                uint32_t bd = base + TILE_SZ + brow * LDT + bcol;
                uint32_t Bh[4], Bl[4];
                ldsm4(Bh, bd);
                ldsm4(Bl, bd + TILE_SZ);
                #pragma unroll
                for (int mt = 0; mt < 4; mt++) {
                    #pragma unroll
                    for (int j = 0; j < 2; j++) {
                        float* cc = C[mt][p * 2 + j];
                        mma_bf16(cc, Ah[mt], Bh[j * 2], Bh[j * 2 + 1]);
                        mma_bf16(cc, Ah[mt], Bl[j * 2], Bl[j * 2 + 1]);
                    }
                }
            }
        }
    }

    // ---- epilogue: bias + routed store (q/skip evict-first, kv default)
    #pragma unroll
    for (int mt = 0; mt < 4; mt++) {
        int m = m0 + wm * 64 + mt * 16 + (lane >> 2);
        #pragma unroll
        for (int nt = 0; nt < 4; nt++) {
            int col = n0 + wn * 32 + nt * 8 + (lane & 3) * 2;
            float b0 = g_bias[col], b1 = g_bias[col + 1];
            int seg = col >> 8;
            #pragma unroll
            for (int h = 0; h < 2; h++) {
                int mm = m + h * 8;
                if (mm >= M) continue;
                float v0 = C[mt][nt][h * 2] + b0;
                float v1 = C[mt][nt][h * 2 + 1] + b1;
                if (seg == 0) {
                    __stcs((float2*)(g_q + (size_t)mm * 256 + col), make_float2(v0, v1));
                } else if (seg == 3) {
                    __stcs((float2*)(g_skip + (size_t)mm * 256 + (col - 768)), make_float2(v0, v1));
                } else {
                    *(__half2*)(g_kv + (size_t)mm * 512 + (col - 256)) = __floats2half2_rn(v0, v1);
                }
            }
        }
    }
}

// ---------------- 4. fused edge attention: 1 warp per dst node --------------
// FROZEN champion: CSR-sorted operands, streaming hints, natural regs.
// Layer-0 output now plain bf16 (no lo split).
__global__ void __launch_bounds__(256) attn_kernel(
    int layer, const float* __restrict__ we, const float* __restrict__ be, int N)
{
    int warp = (int)((blockIdx.x * 256 + threadIdx.x) >> 5);
    int lane = threadIdx.x & 31;
    if (warp >= N) return;

    int d0 = lane * 8;
    float wE[8][6], bE[8];
    #pragma unroll
    for (int i = 0; i < 8; i++) {
        bE[i] = be[d0 + i];
        #pragma unroll
        for (int j = 0; j < 6; j++) wE[i][j] = we[(d0 + i) * 6 + j];
    }

    float q[8];
    {
        const float* qp = g_q + (size_t)warp * 256 + d0;
        float4 t0 = __ldcs((const float4*)qp);
        float4 t1 = __ldcs((const float4*)(qp + 4));
        q[0] = t0.x; q[1] = t0.y; q[2] = t0.z; q[3] = t0.w;
        q[4] = t1.x; q[5] = t1.y; q[6] = t1.z; q[7] = t1.w;
    }

    float qb = 0.f;
    #pragma unroll
    for (int i = 0; i < 8; i++) qb += q[i] * bE[i];
    float qw[6];
    #pragma unroll
    for (int j = 0; j < 6; j++) {
        float t = 0.f;
        #pragma unroll
        for (int i = 0; i < 8; i++) t += q[i] * wE[i][j];
        qw[j] = t;
    }
    #pragma unroll
    for (int off = 16; off; off >>= 1) {
        qb += __shfl_xor_sync(0xffffffffu, qb, off);
        #pragma unroll
        for (int j = 0; j < 6; j++) qw[j] += __shfl_xor_sync(0xffffffffu, qw[j], off);
    }

    float m = -CUDART_INF_F, s = 0.f;
    float acc[8] = {0, 0, 0, 0, 0, 0, 0, 0};
    float te[6]  = {0, 0, 0, 0, 0, 0};
    int p = g_rowptr[warp], end = g_rowptr[warp + 1];

    int src = 0;
    if (p < end) src = g_srcs[p];

    for (; p < end; p++) {
        const __half* kb = g_kv + (size_t)src * 512 + d0;
        uint4 ku = *(const uint4*)kb;
        uint4 vu = *(const uint4*)(kb + 256);
        float e[6];
        #pragma unroll
        for (int j = 0; j < 6; j++) e[j] = __ldg(g_eattr_s + (size_t)p * 6 + j);

        if (p + 1 < end) src = g_srcs[p + 1];

        float qk = 0.f;
        {
            const __half2* kp = (const __half2*)&ku;
            #pragma unroll
            for (int i = 0; i < 4; i++) {
                float2 kf = __half22float2(kp[i]);
                qk += q[i * 2] * kf.x + q[i * 2 + 1] * kf.y;
            }
        }
        #pragma unroll
        for (int off = 16; off; off >>= 1) qk += __shfl_xor_sync(0xffffffffu, qk, off);

        float qe = qb;
        #pragma unroll
        for (int j = 0; j < 6; j++) qe += qw[j] * e[j];
        float logit = (qk + qe) * 0.0625f;

        float nm = fmaxf(m, logit);
        float sc = __expf(m - nm);
        float pw = __expf(logit - nm);
        s = s * sc + pw;
        #pragma unroll
        for (int j = 0; j < 6; j++) te[j] = te[j] * sc + pw * e[j];
        {
            const __half2* vp = (const __half2*)&vu;
            #pragma unroll
            for (int i = 0; i < 4; i++) {
                float2 vf = __half22float2(vp[i]);
                acc[i * 2]     = acc[i * 2]     * sc + pw * vf.x;
                acc[i * 2 + 1] = acc[i * 2 + 1] * sc + pw * vf.y;
            }
        }
        m = nm;
    }

    float inv = (s > 0.f) ? (1.f / s) : 0.f;
    float one = (s > 0.f) ? 1.f : 0.f;
    float tn[6];
    #pragma unroll
    for (int j = 0; j < 6; j++) tn[j] = te[j] * inv;

    const float* sk = g_skip + (size_t)warp * 256 + d0;
    float4 s0 = __ldcs((const float4*)sk);
    float4 s1 = __ldcs((const float4*)(sk + 4));
    float skp[8] = {s0.x, s0.y, s0.z, s0.w, s1.x, s1.y, s1.z, s1.w};

    float o[8];
    #pragma unroll
    for (int i = 0; i < 8; i++) {
        float t = acc[i] * inv + bE[i] * one + skp[i];
        #pragma unroll
        for (int j = 0; j < 6; j++) t += wE[i][j] * tn[j];
        o[i] = fmaxf(t, 0.f);
    }

    if (layer == 0) {
        uint4 uh;
        __nv_bfloat16* ph = (__nv_bfloat16*)&uh;
        #pragma unroll
        for (int i = 0; i < 8; i++) ph[i] = __float2bfloat16(o[i]);
        __stcs((uint4*)(g_hhi + (size_t)warp * 256 + d0), uh);
    } else {
        float* hp = g_h1 + (size_t)warp * 256 + d0;
        __stcs((float4*)hp,       *(const float4*)&o[0]);
        __stcs((float4*)(hp + 4), *(const float4*)&o[4]);
    }
}

// ---------------- 5. pooling (sorted batch, run-accumulated atomics) --------
#define POOL_CHUNK 128
__global__ void __launch_bounds__(256) pool_kernel(const int* __restrict__ batch, int N)
{
    int d  = threadIdx.x;
    int n0 = blockIdx.x * POOL_CHUNK;
    if (n0 >= N) return;
    int n1 = min(n0 + POOL_CHUNK, N);

    int cur = batch[n0];
    float sum = 0.f, mx = 0.f;
    int run = 0;
    for (int n = n0; n < n1; n++) {
        int g = batch[n];
        if (g != cur) {
            atomicAdd(&g_gap[cur * 256 + d], sum);
            atomicMax(&g_gmp[cur * 256 + d], __float_as_uint(mx));
            if (d == 0) atomicAdd(&g_cnt[cur], run);
            sum = 0.f; mx = 0.f; run = 0; cur = g;
        }
        float v = __ldcs(g_h1 + (size_t)n * 256 + d);
        sum += v; mx = fmaxf(mx, v); run++;
    }
    atomicAdd(&g_gap[cur * 256 + d], sum);
    atomicMax(&g_gmp[cur * 256 + d], __float_as_uint(mx));
    if (d == 0) atomicAdd(&g_cnt[cur], run);
}

// ---------------- 6. head MLP ------------------------------------------------
__global__ void __launch_bounds__(256) mlp_kernel(
    const float* __restrict__ w1, const float* __restrict__ b1,
    const float* __restrict__ w2, const float* __restrict__ b2,
    const float* __restrict__ w3, const float* __restrict__ b3,
    float* __restrict__ out)
{
    int g = blockIdx.x;
    int t = threadIdx.x;
    __shared__ float r[512];
    __shared__ float o1[256];
    __shared__ float o2[128];
    __shared__ float red[256];

    float c = fmaxf((float)g_cnt[g], 1.f);
    r[t]       = g_gap[g * 256 + t] / c;
    r[256 + t] = __uint_as_float(g_gmp[g * 256 + t]);
    __syncthreads();
    {
        float a = b1[t];
        const float* wr = w1 + (size_t)t * 512;
        #pragma unroll 8
        for (int i = 0; i < 512; i++) a += wr[i] * r[i];
        o1[t] = fmaxf(a, 0.f);
    }
    __syncthreads();
    if (t < 128) {
        float a = b2[t];
        const float* wr = w2 + (size_t)t * 256;
        #pragma unroll 8
        for (int i = 0; i < 256; i++) a += wr[i] * o1[i];
        o2[t] = fmaxf(a, 0.f);
    }
    __syncthreads();
    red[t] = (t < 128) ? w3[t] * o2[t] : 0.f;
    __syncthreads();
    for (int off = 128; off > 0; off >>= 1) {
        if (t < off) red[t] += red[t + off];
        __syncthreads();
    }
    if (t == 0) out[g] = 1.f / (1.f + __expf(-(red[0] + b3[0])));
}

// ---------------- launch ------------------------------------------------------
extern "C" void kernel_launch(void* const* d_in, const int* in_sizes, int n_in,
                              void* d_out, int out_size)
{
    const int*   x_idx = (const int*)d_in[0];
    const int*   eidx  = (const int*)d_in[1];
    const float* eattr = (const float*)d_in[2];
    const int*   batch = (const int*)d_in[3];
    const float* emb   = (const float*)d_in[4];
    const float* c1[10]; for (int i = 0; i < 10; i++) c1[i] = (const float*)d_in[5 + i];
    const float* c2[10]; for (int i = 0; i < 10; i++) c2[i] = (const float*)d_in[15 + i];
    const float* w1 = (const float*)d_in[25]; const float* b1 = (const float*)d_in[26];
    const float* w2 = (const float*)d_in[27]; const float* b2 = (const float*)d_in[28];
    const float* w3 = (const float*)d_in[29]; const float* b3 = (const float*)d_in[30];

    int N = in_sizes[0] / 8;    // 50000
    int E = in_sizes[1] / 2;    // 300000
    const int* esrc = eidx;
    const int* edst = eidx + E;
    float* out = (float*)d_out;

    cudaFuncSetAttribute(gemm_tc<0>, cudaFuncAttributeMaxDynamicSharedMemorySize, GEMM_SMEM);
    cudaFuncSetAttribute(gemm_tc<1>, cudaFuncAttributeMaxDynamicSharedMemorySize, GEMM_SMEM);

    dim3 ggrid(8, (N + 127) / 128);

    // gemm1 at capture index 3 (verify the 2-term speedup directly).
    embcvt_kernel<<<(VOCAB * 64 + 255) / 256, 256>>>(emb);                             // 0
    splitw_kernel<<<(1024 * 512 + 255) / 256, 256>>>(
        c1[0], c1[2], c1[4], c1[8], c1[1], c1[3], c1[5], c1[9], 512);                  // 1
    csr_kernel<<<CSRB, 256>>>(esrc, edst, eattr, E, N);                                // 2
    gemm_tc<0><<<ggrid, 256, GEMM_SMEM>>>(N, 512, x_idx);                              // 3 <- profiled
    attn_kernel<<<(N + 7) / 8, 256>>>(0, c1[6], c1[7], N);                             // 4
    splitw_kernel<<<(1024 * 256 + 255) / 256, 256>>>(
        c2[0], c2[2], c2[4], c2[8], c2[1], c2[3], c2[5], c2[9], 256);                  // 5
    gemm_tc<1><<<ggrid, 256, GEMM_SMEM>>>(N, 256, nullptr);                            // 6
    attn_kernel<<<(N + 7) / 8, 256>>>(1, c2[6], c2[7], N);                             // 7
    pool_kernel<<<(N + POOL_CHUNK - 1) / POOL_CHUNK, 256>>>(batch, N);                 // 8
    mlp_kernel<<<GNUM, 256>>>(w1, b1, w2, b2, w3, b3, out);                            // 9
}